// round 7
// baseline (speedup 1.0000x reference)
#include <cuda_runtime.h>
#include <cuda_bf16.h>
#include <cstdint>
#include <cstddef>

// Problem constants
#define NROWS 32768          // B*T = 32*1024
#define DDIM  256
#define KCODES 1024

// Output layout (float32, concatenation of reference return tuple)
#define Q_OFF    ((size_t)0)                       // quantized_st : N*D
#define LOSS_OFF ((size_t)8388608)                 // loss : 1
#define IDX_OFF  ((size_t)8388609)                 // indices : N
#define CS_OFF   ((size_t)8421377)                 // new_cluster_size : K
#define EMAW_OFF ((size_t)8422401)                 // new_ema_w : K*D
#define EMB_OFF  ((size_t)8684545)                 // new_embedding : K*D

#define DECAY 0.99f
#define OMD   ((float)(1.0 - 0.99))                // match python double->f32
#define EPS   1e-5f
#define KEPS  (1024.0f * 1e-5f)

// Main-kernel tiling
#define BM 64            // rows per block
#define BN 128           // codes per k-chunk
#define D2 128           // D/2 (float2-packed along d)
#define ZS 66            // zsp row stride in float2 (16B aligned, padded)
#define ES 130           // esp row stride in float2 (16B aligned, padded)
#define DST 8            // d2 per stage
#define NSTAGE 16        // D2/DST stages per k-chunk
#define NKC 8            // K/BN k-chunks

#define ZSP_F2 (D2*ZS)           // 8448 float2
#define ESP_F2 (2*DST*ES)        // 2080 float2
#define SMEM_BYTES ((ZSP_F2+ESP_F2)*8 + BM*4 /*sidx*/ + 8*4 /*lred*/ + BM*4 /*sa*/)

// Scratch (allocation-free rule: __device__ globals)
__device__ __align__(16) float g_e2[KCODES];
__device__ float g_counts[KCODES];
__device__ float g_dw[KCODES * DDIM];
__device__ float g_loss;
__device__ float g_cs[KCODES];

// ---------------------------------------------------------------------------
// packed fp32x2 FMA (PTX-only pattern; doubles FFMA throughput on sm_103a)
__device__ __forceinline__ void ffma2(float2 &d, float2 a, float2 b) {
    unsigned long long dd = *reinterpret_cast<unsigned long long*>(&d);
    unsigned long long aa = *reinterpret_cast<unsigned long long*>(&a);
    unsigned long long bb = *reinterpret_cast<unsigned long long*>(&b);
    asm("fma.rn.f32x2 %0, %1, %2, %0;" : "+l"(dd) : "l"(aa), "l"(bb));
    d = *reinterpret_cast<float2*>(&dd);
}

// ---------------------------------------------------------------------------
__global__ void vq_init() {
    int i = blockIdx.x * blockDim.x + threadIdx.x;
    if (i < KCODES * DDIM) g_dw[i] = 0.0f;
    if (i < KCODES) g_counts[i] = 0.0f;
    if (i == 0) g_loss = 0.0f;
}

__global__ void vq_e2(const float* __restrict__ emb) {
    int k = blockIdx.x;
    float v = emb[k * DDIM + threadIdx.x];
    v *= v;
    for (int off = 16; off; off >>= 1) v += __shfl_down_sync(0xffffffffu, v, off);
    __shared__ float red[8];
    int lane = threadIdx.x & 31, wid = threadIdx.x >> 5;
    if (lane == 0) red[wid] = v;
    __syncthreads();
    if (threadIdx.x == 0) {
        float t = 0.f;
        #pragma unroll
        for (int w = 0; w < 8; w++) t += red[w];
        g_e2[k] = t;
    }
}

// ---------------------------------------------------------------------------
__device__ __forceinline__ float4 ldg_e(const float4* __restrict__ embv, int kc, int st, int idx) {
    int n = idx >> 2, f4 = idx & 3;
    return embv[(size_t)(kc * BN + n) * (DDIM / 4) + st * 4 + f4];
}
__device__ __forceinline__ void sts_e(float2* eb, int idx, float4 v) {
    int n = idx >> 2, f4 = idx & 3;
    eb[(2 * f4) * ES + n]     = make_float2(v.x, v.y);
    eb[(2 * f4 + 1) * ES + n] = make_float2(v.z, v.w);
}

__global__ __launch_bounds__(256, 2)
void vq_main(const float* __restrict__ z, const float* __restrict__ emb,
             float* __restrict__ outq, float* __restrict__ outidx) {
    extern __shared__ char smem_raw[];
    float2* zsp = (float2*)smem_raw;           // [D2][ZS] : z tile, d-pair packed, transposed
    float2* esp = zsp + ZSP_F2;                // [2][DST][ES] : e stage double buffer
    int*   sidx = (int*)(esp + ESP_F2);        // [BM]
    float* lred = (float*)(sidx + BM);         // [8]
    float* sa   = lred + 8;                    // [BM] : ||z_row||^2

    const int tid  = threadIdx.x;
    const int lane = tid & 31;
    const int wid  = tid >> 5;                 // warp id = row-group id
    const int row0 = blockIdx.x * BM;
    const float4* embv = (const float4*)emb;
    const float4* zv4  = (const float4*)z;

    // --- load z tile transposed & d-pair packed ---------------------------
    for (int idx = tid; idx < BM * (DDIM / 4); idx += 256) {
        int m = idx >> 6;              // /64
        int f4 = idx & 63;
        float4 v = zv4[(size_t)(row0 + m) * (DDIM / 4) + f4];
        zsp[(2 * f4) * ZS + m]     = make_float2(v.x, v.y);
        zsp[(2 * f4 + 1) * ZS + m] = make_float2(v.z, v.w);
    }
    // prefetch e stage 0
    float4 pre0 = ldg_e(embv, 0, 0, tid);
    float4 pre1 = ldg_e(embv, 0, 0, tid + 256);
    __syncthreads();

    // store stage 0; compute ||z||^2 per row (warp-owned rows)
    sts_e(esp, tid, pre0);
    sts_e(esp, tid + 256, pre1);
    #pragma unroll
    for (int i = 0; i < 8; i++) {
        int row = wid * 8 + i;
        float s = 0.f;
        #pragma unroll
        for (int u = 0; u < 4; u++) {
            float2 p = zsp[(lane + u * 32) * ZS + row];
            s = fmaf(p.x, p.x, fmaf(p.y, p.y, s));
        }
        for (int off = 16; off; off >>= 1) s += __shfl_down_sync(0xffffffffu, s, off);
        if (lane == 0) sa[row] = s;
    }
    __syncthreads();

    // --- main loop: dot(z_row, e_code) with running argmin ----------------
    float bestv[8]; int besti[8];
    #pragma unroll
    for (int i = 0; i < 8; i++) { bestv[i] = 3.402823466e38f; besti[i] = 0; }
    float2 acc[8][4];
    #pragma unroll
    for (int i = 0; i < 8; i++)
        #pragma unroll
        for (int j = 0; j < 4; j++) acc[i][j] = make_float2(0.f, 0.f);

    int buf = 0;
    for (int kc = 0; kc < NKC; kc++) {
        for (int st = 0; st < NSTAGE; st++) {
            bool hn = (kc < NKC - 1) || (st < NSTAGE - 1);
            if (hn) {
                int nkc = kc, nst = st + 1;
                if (nst == NSTAGE) { nst = 0; nkc++; }
                pre0 = ldg_e(embv, nkc, nst, tid);
                pre1 = ldg_e(embv, nkc, nst, tid + 256);
            }
            const float2* eb = esp + buf * (DST * ES);
            #pragma unroll
            for (int dd = 0; dd < DST; dd++) {
                const float2* zr = zsp + (st * DST + dd) * ZS + wid * 8;
                float2 a2[8];
                #pragma unroll
                for (int i = 0; i < 8; i += 2) {
                    float4 t = *reinterpret_cast<const float4*>(zr + i);
                    a2[i]     = make_float2(t.x, t.y);
                    a2[i + 1] = make_float2(t.z, t.w);
                }
                const float2* er = eb + dd * ES + lane * 4;
                float4 t0 = *reinterpret_cast<const float4*>(er);
                float4 t1 = *reinterpret_cast<const float4*>(er + 2);
                float2 b2[4] = { make_float2(t0.x, t0.y), make_float2(t0.z, t0.w),
                                 make_float2(t1.x, t1.y), make_float2(t1.z, t1.w) };
                #pragma unroll
                for (int i = 0; i < 8; i++)
                    #pragma unroll
                    for (int j = 0; j < 4; j++) ffma2(acc[i][j], a2[i], b2[j]);
            }
            __syncthreads();
            if (hn) {
                sts_e(esp + (buf ^ 1) * (DST * ES), tid, pre0);
                sts_e(esp + (buf ^ 1) * (DST * ES), tid + 256, pre1);
                buf ^= 1;
                __syncthreads();
            }
        }
        // scores for this k-chunk, replicating jax rounding:
        // dist = fl( fl(||z||^2 + ||e||^2) - fl(2*dot) )
        float4 e2v = *reinterpret_cast<const float4*>(&g_e2[kc * BN + lane * 4]);
        float e2a[4] = { e2v.x, e2v.y, e2v.z, e2v.w };
        #pragma unroll
        for (int i = 0; i < 8; i++) {
            float an = sa[wid * 8 + i];
            #pragma unroll
            for (int j = 0; j < 4; j++) {
                float dot = acc[i][j].x + acc[i][j].y;
                float t1 = an + e2a[j];
                float sc = t1 - 2.0f * dot;
                int code = kc * BN + lane * 4 + j;
                if (sc < bestv[i]) { bestv[i] = sc; besti[i] = code; }
                acc[i][j] = make_float2(0.f, 0.f);
            }
        }
    }

    // --- warp argmin reduce (first-min tie-break like jnp.argmin) ---------
    #pragma unroll
    for (int i = 0; i < 8; i++) {
        float v = bestv[i]; int ix = besti[i];
        for (int off = 16; off; off >>= 1) {
            float ov = __shfl_down_sync(0xffffffffu, v, off);
            int   oi = __shfl_down_sync(0xffffffffu, ix, off);
            if (ov < v || (ov == v && oi < ix)) { v = ov; ix = oi; }
        }
        if (lane == 0) {
            sidx[wid * 8 + i] = ix;
            outidx[row0 + wid * 8 + i] = (float)ix;
        }
    }
    __syncthreads();

    // --- epilogue: quantized gather, loss, counts, dw scatter -------------
    float lsum = 0.f;
    const int d = tid;  // 256 threads == DDIM
    for (int r = 0; r < BM; r++) {
        int code = sidx[r];
        size_t go = (size_t)(row0 + r) * DDIM + d;
        float q  = emb[(size_t)code * DDIM + d];
        float zvv = z[go];
        outq[go] = q;
        float df = zvv - q;
        lsum = fmaf(df, df, lsum);
        atomicAdd(&g_dw[code * DDIM + d], zvv);
    }
    if (tid < BM) atomicAdd(&g_counts[sidx[tid]], 1.0f);

    for (int off = 16; off; off >>= 1) lsum += __shfl_down_sync(0xffffffffu, lsum, off);
    if (lane == 0) lred[wid] = lsum;
    __syncthreads();
    if (tid == 0) {
        float t = 0.f;
        #pragma unroll
        for (int w = 0; w < 8; w++) t += lred[w];
        atomicAdd(&g_loss, t);
    }
}

// ---------------------------------------------------------------------------
__global__ void vq_finalize(const float* __restrict__ ema_cs, float* __restrict__ out) {
    int k = threadIdx.x;  // 1024 threads
    float pre = ema_cs[k] * DECAY + OMD * g_counts[k];
    // block-reduce sum -> n
    __shared__ float sred[32];
    float v = pre;
    int lane = k & 31, wid = k >> 5;
    for (int off = 16; off; off >>= 1) v += __shfl_down_sync(0xffffffffu, v, off);
    if (lane == 0) sred[wid] = v;
    __syncthreads();
    if (wid == 0) {
        float t = sred[lane];
        for (int off = 16; off; off >>= 1) t += __shfl_down_sync(0xffffffffu, t, off);
        if (lane == 0) sred[0] = t;
    }
    __syncthreads();
    float n = sred[0];
    float cs = (pre + EPS) / (n + KEPS) * n;
    out[CS_OFF + k] = cs;
    g_cs[k] = cs;
    if (k == 0) out[LOSS_OFF] = 0.25f * g_loss / (float)(NROWS * DDIM);
}

__global__ void vq_emaw(const float* __restrict__ ema_w, float* __restrict__ out) {
    int i = blockIdx.x * 256 + threadIdx.x;   // < K*D
    int k = i >> 8;
    float w = ema_w[i] * DECAY + OMD * g_dw[i];
    out[EMAW_OFF + i] = w;
    out[EMB_OFF + i] = w / g_cs[k];
}

// ---------------------------------------------------------------------------
extern "C" void kernel_launch(void* const* d_in, const int* in_sizes, int n_in,
                              void* d_out, int out_size) {
    const float* z      = (const float*)d_in[0];  // [32,1024,256]
    const float* emb    = (const float*)d_in[1];  // [1024,256]
    const float* ema_cs = (const float*)d_in[2];  // [1024]
    const float* ema_w  = (const float*)d_in[3];  // [1024,256]
    float* out = (float*)d_out;

    static bool attr_set = false;
    // idempotent, deterministic; required for >48KB dynamic smem
    cudaFuncSetAttribute(vq_main, cudaFuncAttributeMaxDynamicSharedMemorySize, SMEM_BYTES);
    (void)attr_set; (void)in_sizes; (void)n_in; (void)out_size;

    vq_init<<<(KCODES * DDIM + 255) / 256, 256>>>();
    vq_e2<<<KCODES, 256>>>(emb);
    vq_main<<<NROWS / BM, 256, SMEM_BYTES>>>(z, emb, out + Q_OFF, out + IDX_OFF);
    vq_finalize<<<1, 1024>>>(ema_cs, out);
    vq_emaw<<<KCODES * DDIM / 256, 256>>>(ema_w, out);
}

// round 8
// speedup vs baseline: 1.1799x; 1.1799x over previous
#include <cuda_runtime.h>
#include <cuda_bf16.h>
#include <cstdint>
#include <cstddef>

// Problem constants
#define NROWS 32768          // B*T = 32*1024
#define DDIM  256
#define KCODES 1024

// Output layout (float32, concatenation of reference return tuple)
#define Q_OFF    ((size_t)0)                       // quantized_st : N*D
#define LOSS_OFF ((size_t)8388608)                 // loss : 1
#define IDX_OFF  ((size_t)8388609)                 // indices : N
#define CS_OFF   ((size_t)8421377)                 // new_cluster_size : K
#define EMAW_OFF ((size_t)8422401)                 // new_ema_w : K*D
#define EMB_OFF  ((size_t)8684545)                 // new_embedding : K*D

#define DECAY 0.99f
#define OMD   ((float)(1.0 - 0.99))
#define EPS   1e-5f
#define KEPS  (1024.0f * 1e-5f)

// Main-kernel tiling
#define BM 64            // rows per block
#define BN 128           // codes per k-chunk
#define D2 128           // D/2 (float2-packed along d)
#define ZS 66            // zsp row stride in float2 (16B aligned, padded)
#define DST 8            // d2 per e-stage
#define NSTAGE 16        // D2/DST stages per k-chunk
#define NKC 8            // K/BN k-chunks
#define NTHR 128         // threads per CTA (4 warps)

#define ZSP_F2 (D2*ZS)            // 8448 float2 = 67584 B
#define ESP_F4 (2*DST*BN/2)       // 2 bufs * 512 float4 = 16384 B
#define SMEM_BYTES (ZSP_F2*8 + ESP_F4*16 + BM*4 + BM*4 + 4*4)   // 84496

// Scratch (allocation-free rule: __device__ globals)
__device__ __align__(16) float g_e2[KCODES];
__device__ float g_counts[KCODES];
__device__ float g_dw[KCODES * DDIM];
__device__ float g_loss;
__device__ float g_cs[KCODES];

// ---------------------------------------------------------------------------
// packed fp32x2 FMA (PTX-only pattern; doubles FFMA throughput on sm_103a)
__device__ __forceinline__ void ffma2(float2 &d, float2 a, float2 b) {
    unsigned long long dd = *reinterpret_cast<unsigned long long*>(&d);
    unsigned long long aa = *reinterpret_cast<unsigned long long*>(&a);
    unsigned long long bb = *reinterpret_cast<unsigned long long*>(&b);
    asm("fma.rn.f32x2 %0, %1, %2, %0;" : "+l"(dd) : "l"(aa), "l"(bb));
    d = *reinterpret_cast<float2*>(&dd);
}

// e-tile swizzle: logical float4 (dd, n4) -> physical float4 index.
// dd*64 aligns to 128B rows, so only n4's high bits feed the XOR.
// Verified conflict-free for both the 4x LDS.128 (n4 = 4*lc+b) and the
// staging STS.64 pattern.
__device__ __forceinline__ int esw(int dd, int n4) {
    return dd * 64 + (n4 & ~7) + ((n4 & 7) ^ ((n4 >> 3) & 7));
}

// ---------------------------------------------------------------------------
__global__ void vq_init() {
    int i = blockIdx.x * blockDim.x + threadIdx.x;
    if (i < KCODES * DDIM) g_dw[i] = 0.0f;
    if (i < KCODES) g_counts[i] = 0.0f;
    if (i == 0) g_loss = 0.0f;
}

__global__ void vq_nop() {}   // slot-shifter so ncu -s5 lands on vq_main

__global__ void vq_e2(const float* __restrict__ emb) {
    int k = blockIdx.x;
    float v = emb[k * DDIM + threadIdx.x];
    v *= v;
    for (int off = 16; off; off >>= 1) v += __shfl_down_sync(0xffffffffu, v, off);
    __shared__ float red[8];
    int lane = threadIdx.x & 31, wid = threadIdx.x >> 5;
    if (lane == 0) red[wid] = v;
    __syncthreads();
    if (threadIdx.x == 0) {
        float t = 0.f;
        #pragma unroll
        for (int w = 0; w < 8; w++) t += red[w];
        g_e2[k] = t;
    }
}

// ---------------------------------------------------------------------------
// stage store: thread t owns code n=t; its 4 gmem float4s cover dd = 2j, 2j+1
__device__ __forceinline__ void sts_stage(float2* eb, int t, const float4* pre) {
    int n4 = t >> 1, half = t & 1;
    #pragma unroll
    for (int j = 0; j < 4; j++) {
        float4 v = pre[j];
        eb[esw(2 * j, n4) * 2 + half]     = make_float2(v.x, v.y);
        eb[esw(2 * j + 1, n4) * 2 + half] = make_float2(v.z, v.w);
    }
}

__global__ __launch_bounds__(NTHR, 2)
void vq_main(const float* __restrict__ z, const float* __restrict__ emb,
             float* __restrict__ outq, float* __restrict__ outidx) {
    extern __shared__ char smem_raw[];
    float2* zsp  = (float2*)smem_raw;            // [D2][ZS] z tile, d-pair packed, transposed
    float4* esp4 = (float4*)(zsp + ZSP_F2);      // 2 x 512 float4 swizzled e stages
    int*   sidx  = (int*)(esp4 + ESP_F4);        // [BM]
    float* sa    = (float*)(sidx + BM);          // [BM] ||z_row||^2
    float* lred  = sa + BM;                      // [4]

    const int tid  = threadIdx.x;
    const int lane = tid & 31;
    const int warp = tid >> 5;                   // 0..3 -> 16 rows each
    const int lr   = lane >> 4;                  // 0..1 -> 8-row subgroup
    const int lc   = lane & 15;                  // 0..15 -> 8-code group
    const int row0 = blockIdx.x * BM;
    const float4* embv = (const float4*)emb;
    const float4* zv4  = (const float4*)z;

    // per-thread e-load swizzle constants: n4 = 4*lc + b
    const int e_base = 8 * (lc >> 1);            // n4 & ~7
    const int e_xor  = (lc >> 1) & 7;            // (n4>>3)&7
    const int e_cb   = 4 * (lc & 1);             // n4&7 minus b

    // --- load z tile transposed & d-pair packed ---------------------------
    for (int idx = tid; idx < BM * (DDIM / 4); idx += NTHR) {
        int m = idx >> 6;
        int f4 = idx & 63;
        float4 v = zv4[(size_t)(row0 + m) * (DDIM / 4) + f4];
        zsp[(2 * f4) * ZS + m]     = make_float2(v.x, v.y);
        zsp[(2 * f4 + 1) * ZS + m] = make_float2(v.z, v.w);
    }
    // prefetch e stage (kc=0, st=0): thread t owns code t, 4 float4
    float4 pre[4];
    #pragma unroll
    for (int j = 0; j < 4; j++)
        pre[j] = embv[(size_t)tid * (DDIM / 4) + j];
    __syncthreads();

    // store stage 0; compute ||z||^2 per row
    sts_stage((float2*)esp4, tid, pre);
    for (int i = 0; i < 16; i++) {
        int row = warp * 16 + i;
        float s = 0.f;
        #pragma unroll
        for (int u = 0; u < 4; u++) {
            float2 p = zsp[(lane + u * 32) * ZS + row];
            s = fmaf(p.x, p.x, fmaf(p.y, p.y, s));
        }
        for (int off = 16; off; off >>= 1) s += __shfl_down_sync(0xffffffffu, s, off);
        if (lane == 0) sa[row] = s;
    }
    __syncthreads();

    // --- main loop --------------------------------------------------------
    float bestv[8]; int besti[8];
    #pragma unroll
    for (int i = 0; i < 8; i++) { bestv[i] = 3.402823466e38f; besti[i] = 0; }
    float2 acc[8][8];
    #pragma unroll
    for (int i = 0; i < 8; i++)
        #pragma unroll
        for (int j = 0; j < 8; j++) acc[i][j] = make_float2(0.f, 0.f);

    int buf = 0;
    for (int kc = 0; kc < NKC; kc++) {
        #pragma unroll 1
        for (int st = 0; st < NSTAGE; st++) {
            bool hn = !(kc == NKC - 1 && st == NSTAGE - 1);
            if (hn) {
                int nkc = kc, nst = st + 1;
                if (nst == NSTAGE) { nst = 0; nkc++; }
                #pragma unroll
                for (int j = 0; j < 4; j++)
                    pre[j] = embv[(size_t)(nkc * BN + tid) * (DDIM / 4) + nst * 4 + j];
            }
            const float4* eb4 = esp4 + buf * (ESP_F4 / 2);
            #pragma unroll
            for (int dd = 0; dd < DST; dd++) {
                // z: 8 rows (float2 each), broadcast within 16-lane groups
                const float2* zr = zsp + (st * DST + dd) * ZS + warp * 16 + lr * 8;
                float2 a2[8];
                #pragma unroll
                for (int i = 0; i < 8; i += 2) {
                    float4 t = *reinterpret_cast<const float4*>(zr + i);
                    a2[i]     = make_float2(t.x, t.y);
                    a2[i + 1] = make_float2(t.z, t.w);
                }
                // e: 8 codes (float2 each), swizzled conflict-free
                float2 b2[8];
                #pragma unroll
                for (int b = 0; b < 4; b++) {
                    float4 v = eb4[dd * 64 + e_base + ((e_cb + b) ^ e_xor)];
                    b2[2 * b]     = make_float2(v.x, v.y);
                    b2[2 * b + 1] = make_float2(v.z, v.w);
                }
                #pragma unroll
                for (int i = 0; i < 8; i++)
                    #pragma unroll
                    for (int j = 0; j < 8; j++) ffma2(acc[i][j], a2[i], b2[j]);
            }
            __syncthreads();
            if (hn) {
                sts_stage((float2*)(esp4 + (buf ^ 1) * (ESP_F4 / 2)), tid, pre);
                buf ^= 1;
                __syncthreads();
            }
        }
        // scores for this k-chunk, replicating jax rounding:
        // dist = fl( fl(||z||^2 + ||e||^2) - fl(2*dot) )
        float4 e2lo = *reinterpret_cast<const float4*>(&g_e2[kc * BN + lc * 8]);
        float4 e2hi = *reinterpret_cast<const float4*>(&g_e2[kc * BN + lc * 8 + 4]);
        float e2a[8] = { e2lo.x, e2lo.y, e2lo.z, e2lo.w, e2hi.x, e2hi.y, e2hi.z, e2hi.w };
        #pragma unroll
        for (int i = 0; i < 8; i++) {
            float an = sa[warp * 16 + lr * 8 + i];
            #pragma unroll
            for (int j = 0; j < 8; j++) {
                float dot = acc[i][j].x + acc[i][j].y;
                float t1 = an + e2a[j];
                float sc = t1 - 2.0f * dot;
                int code = kc * BN + lc * 8 + j;
                if (sc < bestv[i]) { bestv[i] = sc; besti[i] = code; }
                acc[i][j] = make_float2(0.f, 0.f);
            }
        }
    }

    // --- argmin reduce across the 16 lc lanes (first-min tie-break) -------
    #pragma unroll
    for (int i = 0; i < 8; i++) {
        float v = bestv[i]; int ix = besti[i];
        #pragma unroll
        for (int off = 8; off; off >>= 1) {
            float ov = __shfl_down_sync(0xffffffffu, v, off, 16);
            int   oi = __shfl_down_sync(0xffffffffu, ix, off, 16);
            if (ov < v || (ov == v && oi < ix)) { v = ov; ix = oi; }
        }
        if (lc == 0) {
            int row = warp * 16 + lr * 8 + i;
            sidx[row] = ix;
            outidx[row0 + row] = (float)ix;
        }
    }
    __syncthreads();

    // --- epilogue: quantized gather, loss, counts, dw scatter -------------
    float lsum = 0.f;
    const int d0 = tid * 2;   // 128 threads x 2 floats = DDIM
    for (int r = 0; r < BM; r++) {
        int code = sidx[r];
        size_t go = (size_t)(row0 + r) * DDIM + d0;
        float2 q  = *reinterpret_cast<const float2*>(&emb[(size_t)code * DDIM + d0]);
        float2 zv = *reinterpret_cast<const float2*>(&z[go]);
        *reinterpret_cast<float2*>(&outq[go]) = q;
        float dx = zv.x - q.x, dy = zv.y - q.y;
        lsum = fmaf(dx, dx, fmaf(dy, dy, lsum));
        atomicAdd(&g_dw[code * DDIM + d0], zv.x);
        atomicAdd(&g_dw[code * DDIM + d0 + 1], zv.y);
    }
    if (tid < BM) atomicAdd(&g_counts[sidx[tid]], 1.0f);

    for (int off = 16; off; off >>= 1) lsum += __shfl_down_sync(0xffffffffu, lsum, off);
    if (lane == 0) lred[warp] = lsum;
    __syncthreads();
    if (tid == 0) {
        float t = 0.f;
        #pragma unroll
        for (int w = 0; w < 4; w++) t += lred[w];
        atomicAdd(&g_loss, t);
    }
}

// ---------------------------------------------------------------------------
__global__ void vq_finalize(const float* __restrict__ ema_cs, float* __restrict__ out) {
    int k = threadIdx.x;  // 1024 threads
    float pre = ema_cs[k] * DECAY + OMD * g_counts[k];
    __shared__ float sred[32];
    float v = pre;
    int lane = k & 31, wid = k >> 5;
    for (int off = 16; off; off >>= 1) v += __shfl_down_sync(0xffffffffu, v, off);
    if (lane == 0) sred[wid] = v;
    __syncthreads();
    if (wid == 0) {
        float t = sred[lane];
        for (int off = 16; off; off >>= 1) t += __shfl_down_sync(0xffffffffu, t, off);
        if (lane == 0) sred[0] = t;
    }
    __syncthreads();
    float n = sred[0];
    float cs = (pre + EPS) / (n + KEPS) * n;
    out[CS_OFF + k] = cs;
    g_cs[k] = cs;
    if (k == 0) out[LOSS_OFF] = 0.25f * g_loss / (float)(NROWS * DDIM);
}

__global__ void vq_emaw(const float* __restrict__ ema_w, float* __restrict__ out) {
    int i = blockIdx.x * 256 + threadIdx.x;   // < K*D
    int k = i >> 8;
    float w = ema_w[i] * DECAY + OMD * g_dw[i];
    out[EMAW_OFF + i] = w;
    out[EMB_OFF + i] = w / g_cs[k];
}

// ---------------------------------------------------------------------------
extern "C" void kernel_launch(void* const* d_in, const int* in_sizes, int n_in,
                              void* d_out, int out_size) {
    const float* z      = (const float*)d_in[0];  // [32,1024,256]
    const float* emb    = (const float*)d_in[1];  // [1024,256]
    const float* ema_cs = (const float*)d_in[2];  // [1024]
    const float* ema_w  = (const float*)d_in[3];  // [1024,256]
    float* out = (float*)d_out;

    cudaFuncSetAttribute(vq_main, cudaFuncAttributeMaxDynamicSharedMemorySize, SMEM_BYTES);
    (void)in_sizes; (void)n_in; (void)out_size;

    vq_init<<<(KCODES * DDIM + 255) / 256, 256>>>();
    vq_e2<<<KCODES, 256>>>(emb);
    vq_nop<<<1, 32>>>();                             // shifts ncu -s5 slot onto vq_main
    vq_main<<<NROWS / BM, NTHR, SMEM_BYTES>>>(z, emb, out + Q_OFF, out + IDX_OFF);
    vq_finalize<<<1, 1024>>>(ema_cs, out);
    vq_emaw<<<KCODES * DDIM / 256, 256>>>(ema_w, out);
}